// round 12
// baseline (speedup 1.0000x reference)
#include <cuda_runtime.h>
#include <cuda_bf16.h>
#include <cstdint>

#define NN 131072
#define NE 262144
#define DD 128
#define LL 5

// ------------------------- scratch (device globals) ------------------------
__device__ float g_h0[(size_t)NN * DD];
__device__ float g_bufA[(size_t)NN * DD];
__device__ float g_bufB[(size_t)NN * DD];
__device__ uint32_t g_w1h[LL * 256 * 64];   // [l][n][k2] bf16x2 hi
__device__ uint32_t g_w1l[LL * 256 * 64];
__device__ uint32_t g_w2h[LL * 128 * 128];
__device__ uint32_t g_w2l[LL * 128 * 128];
__device__ double g_sumsd[256];
__device__ float g_ss[256];
// CSR scratch
__device__ int g_deg[NN];                   // degree -> cursor
__device__ int g_rowptr[NN + 1];
__device__ int g_eperm[NE];                 // src | (combo<<17)

// ------------------------- helpers -----------------------------------------
__device__ __forceinline__ uint32_t sm2u(const void* p) {
    uint32_t a;
    asm("{ .reg .u64 t; cvta.to.shared.u64 t, %1; cvt.u32.u64 %0, t; }" : "=r"(a) : "l"(p));
    return a;
}
#define LDSM4(d0, d1, d2, d3, a) \
    asm volatile("ldmatrix.sync.aligned.m8n8.x4.shared.b16 {%0,%1,%2,%3}, [%4];" \
                 : "=r"(d0), "=r"(d1), "=r"(d2), "=r"(d3) : "r"(a))
#define CPASYNC16(dst, src) \
    asm volatile("cp.async.cg.shared.global [%0], [%1], 16;" :: "r"(dst), "l"(src) : "memory")
#define CPCOMMIT() asm volatile("cp.async.commit_group;" ::: "memory")
#define CPWAIT0()  asm volatile("cp.async.wait_group 0;" ::: "memory")

__device__ __forceinline__ void split2(float v0, float v1, uint32_t& hi, uint32_t& lo) {
    __nv_bfloat16 h0 = __float2bfloat16_rn(v0), h1 = __float2bfloat16_rn(v1);
    __nv_bfloat162 hp; hp.x = h0; hp.y = h1;
    hi = *(uint32_t*)&hp;
    float l0 = v0 - __bfloat162float(h0), l1 = v1 - __bfloat162float(h1);
    __nv_bfloat162 lp = __floats2bfloat162_rn(l0, l1);
    lo = *(uint32_t*)&lp;
}
__device__ __forceinline__ void mma_bf16(float* d, const uint32_t* a, const uint32_t* b) {
    asm volatile(
        "mma.sync.aligned.m16n8k16.row.col.f32.bf16.bf16.f32 "
        "{%0,%1,%2,%3}, {%4,%5,%6,%7}, {%8,%9}, {%0,%1,%2,%3};"
        : "+f"(d[0]), "+f"(d[1]), "+f"(d[2]), "+f"(d[3])
        : "r"(a[0]), "r"(a[1]), "r"(a[2]), "r"(a[3]), "r"(b[0]), "r"(b[1]));
}

// ------------------------- prep: weights + zeroing --------------------------
__global__ void k_prep(const float* __restrict__ W1, const float* __restrict__ W2) {
    int i = blockIdx.x * 256 + threadIdx.x;              // 640*256 = 163840
    if (i < 81920) {
        int l = i / 16384, r = i - l * 16384;
        int n = r >> 6, k2 = r & 63;
        float w0 = W1[l * 32768 + (2 * k2) * 256 + n];
        float w1 = W1[l * 32768 + (2 * k2 + 1) * 256 + n];
        uint32_t hi, lo; split2(w0, w1, hi, lo);
        g_w1h[i] = hi; g_w1l[i] = lo;
    } else {
        int j = i - 81920;
        int l = j / 16384, r = j - l * 16384;
        int n = r >> 7, k2 = r & 127;
        float w0 = W2[l * 32768 + (2 * k2) * 128 + n];
        float w1 = W2[l * 32768 + (2 * k2 + 1) * 128 + n];
        uint32_t hi, lo; split2(w0, w1, hi, lo);
        g_w2h[j] = hi; g_w2l[j] = lo;
    }
    if (i < NN) g_deg[i] = 0;
    if (i < 128) { g_sumsd[2 * i] = 0.0; g_sumsd[2 * i + 1] = 0.0; }
}

// ------------------------- init h0 + edge histogram -------------------------
__global__ void k_inithist(const int* __restrict__ x, const float* __restrict__ xe1,
                           const float* __restrict__ xe2, const int* __restrict__ ei) {
    int t = blockIdx.x * 256 + threadIdx.x;              // NN*32
    int row = t >> 5, c4 = t & 31;
    int i0 = x[2 * row], i1 = x[2 * row + 1];
    float4 a = ((const float4*)xe1)[i0 * 32 + c4];
    float4 b = ((const float4*)xe2)[i1 * 32 + c4];
    ((float4*)g_h0)[t] = make_float4(a.x + b.x, a.y + b.y, a.z + b.z, a.w + b.w);
    if (t < NE) atomicAdd(&g_deg[ei[NE + t]], 1);
}

// ------------------------- scan + place (single block) ----------------------
__global__ void __launch_bounds__(1024) k_scanplace(const int* __restrict__ ei,
                                                    const int* __restrict__ ea) {
    __shared__ int ssum[1024];
    int t = threadIdx.x;
    int base = t * 128;                                  // 1024*128 = NN
    int s = 0;
    for (int k = 0; k < 128; k++) s += g_deg[base + k];
    ssum[t] = s;
    __syncthreads();
    #pragma unroll
    for (int off = 1; off < 1024; off <<= 1) {
        int v = (t >= off) ? ssum[t - off] : 0;
        __syncthreads();
        ssum[t] += v;
        __syncthreads();
    }
    int run = (t > 0) ? ssum[t - 1] : 0;                 // exclusive block prefix
    for (int k = 0; k < 128; k++) {
        int d = g_deg[base + k];
        g_rowptr[base + k] = run;                        // rowptr[i] = start
        g_deg[base + k] = run;                           // cursor
        run += d;
    }
    if (t == 1023) g_rowptr[NN] = run;
    __syncthreads();
    for (int e = t; e < NE; e += 1024) {
        int dst = ei[NE + e];
        int src = ei[e];
        int combo = ea[2 * e] * 3 + ea[2 * e + 1];
        int pos = atomicAdd(&g_deg[dst], 1);
        g_eperm[pos] = src | (combo << 17);
    }
}

// ------------------------- BN stats / final ---------------------------------
__global__ void k_stats(const float* __restrict__ gamma, const float* __restrict__ beta) {
    int c = threadIdx.x;
    double su = g_sumsd[c], sq = g_sumsd[128 + c];
    double mu  = su * (1.0 / NN);
    double var = sq * (1.0 / NN) - mu * mu;
    float sc = (float)(rsqrt(var + 1e-5) * (double)gamma[c]);
    g_ss[c] = sc;
    g_ss[128 + c] = (float)((double)beta[c] - mu * (double)sc);
    g_sumsd[c] = 0.0; g_sumsd[128 + c] = 0.0;
}
__global__ void k_final(float* __restrict__ out) {
    int t = blockIdx.x * 256 + threadIdx.x;
    int c4 = t & 31;
    float4 v = ((const float4*)g_bufA)[t];
    float4 s = ((const float4*)g_ss)[c4];
    float4 b = ((const float4*)g_ss)[32 + c4];
    ((float4*)out)[t] = make_float4(fmaf(v.x, s.x, b.x), fmaf(v.y, s.y, b.y),
                                    fmaf(v.z, s.z, b.z), fmaf(v.w, s.w, b.w));
}

// ------------------------- fused agg + MLP + BN sums ------------------------
#define A1H_OFF 0           // 128 x 68 u32   (agg out hi)     [phase 1]
#define A1L_OFF 34816
#define B1H_OFF 69632       // 256 x 68 u32   (W1 full)        [phase 1]
#define B1L_OFF 139264
#define A2H_OFF 0           // 128 x 132 u32  (GEMM1 out hi)   [phase 2]
#define A2L_OFF 67584
#define A2_S    132
#define B2H_OFF 135168      // 128 x 20 u32   (W2 chunk)       [phase 2]
#define B2L_OFF 145408
#define SB_OFF  208896      // 384 floats
#define BND_OFF 210432      // 256 doubles
#define COMB_OFF 212480     // 18*32 float4
#define SM_TOT  221696

__global__ void __launch_bounds__(512, 1) k_fused(
    int src_sel, int dst_sel,
    const float* __restrict__ e1, const float* __restrict__ e2,
    const float* __restrict__ b1p, const float* __restrict__ b2p,
    int affine, int layer)
{
    extern __shared__ char smem[];
    uint32_t* A1H = (uint32_t*)(smem + A1H_OFF);
    uint32_t* A1L = (uint32_t*)(smem + A1L_OFF);
    uint32_t* A2H = (uint32_t*)(smem + A2H_OFF);
    uint32_t* A2L = (uint32_t*)(smem + A2L_OFF);
    uint32_t* B2H = (uint32_t*)(smem + B2H_OFF);
    uint32_t* B2L = (uint32_t*)(smem + B2L_OFF);
    float*    sb  = (float*)(smem + SB_OFF);
    double*   bnd = (double*)(smem + BND_OFF);
    float4*   comb = (float4*)(smem + COMB_OFF);
    const int tid = threadIdx.x, w = tid >> 5, lane = tid & 31;
    const int g = lane >> 2, tig = lane & 3;
    const int wm = w & 3, wn = w >> 2;
    const uint32_t* w1h = g_w1h + layer * 16384;
    const uint32_t* w1l = g_w1l + layer * 16384;
    const uint32_t* w2h = g_w2h + layer * 16384;
    const uint32_t* w2l = g_w2l + layer * 16384;
    const size_t rowbase = (size_t)blockIdx.x * 128;
    const float* hsrc = (src_sel == 0) ? g_h0 : (src_sel == 1 ? g_bufA : g_bufB);
    float* hout = (dst_sel == 1) ? g_bufA : g_bufB;

    // ---- issue cp.async of full W1 (overlaps aggregation) ----
    const uint32_t b1hS = sm2u(smem + B1H_OFF), b1lS = sm2u(smem + B1L_OFF);
    #pragma unroll
    for (int it = 0; it < 8; it++) {
        int i = it * 512 + tid, r = i >> 4, seg = (i & 15) * 4;
        CPASYNC16(b1hS + (r * 68 + seg) * 4, w1h + r * 64 + seg);
        CPASYNC16(b1lS + (r * 68 + seg) * 4, w1l + r * 64 + seg);
    }
    CPCOMMIT();

    // ---- small tables ----
    if (tid < 384) sb[tid] = (tid < 256) ? b1p[tid] : b2p[tid - 256];
    if (tid < 256) bnd[tid] = 0.0;
    {
        const float4* e14 = (const float4*)e1;
        const float4* e24 = (const float4*)e2;
        for (int i = tid; i < 576; i += 512) {
            int cb = i >> 5, c4 = i & 31;
            int a0 = cb / 3, a1 = cb - a0 * 3;
            float4 v1 = e14[a0 * 32 + c4];
            float4 v2 = e24[a1 * 32 + c4];
            comb[i] = make_float4(v1.x + v2.x, v1.y + v2.y, v1.z + v2.z, v1.w + v2.w);
        }
    }
    __syncthreads();

    // ---- aggregation phase: warp w -> nodes rowbase + 8w .. +8 ----
    {
        float4 s4, h4;
        if (affine) { s4 = ((const float4*)g_ss)[lane]; h4 = ((const float4*)g_ss)[32 + lane]; }
        else { s4 = make_float4(1.f, 1.f, 1.f, 1.f); h4 = make_float4(0.f, 0.f, 0.f, 0.f); }
        const float4* src4 = (const float4*)hsrc;
        for (int j = 0; j < 8; j++) {
            int node = (int)rowbase + w * 8 + j;
            float4 v = src4[(size_t)node * 32 + lane];
            float4 acc;
            if (affine) {
                acc.x = fmaxf(fmaf(v.x, s4.x, h4.x), 0.f);
                acc.y = fmaxf(fmaf(v.y, s4.y, h4.y), 0.f);
                acc.z = fmaxf(fmaf(v.z, s4.z, h4.z), 0.f);
                acc.w = fmaxf(fmaf(v.w, s4.w, h4.w), 0.f);
            } else acc = v;
            float4 cm = comb[12 * 32 + lane];
            acc.x += cm.x; acc.y += cm.y; acc.z += cm.z; acc.w += cm.w;
            int beg = g_rowptr[node], end = g_rowptr[node + 1];
            int e = beg;
            for (; e + 3 < end; e += 4) {
                int p0 = g_eperm[e],     p1 = g_eperm[e + 1];
                int p2 = g_eperm[e + 2], p3 = g_eperm[e + 3];
                float4 u0 = src4[(size_t)(p0 & 0x1FFFF) * 32 + lane];
                float4 u1 = src4[(size_t)(p1 & 0x1FFFF) * 32 + lane];
                float4 u2 = src4[(size_t)(p2 & 0x1FFFF) * 32 + lane];
                float4 u3 = src4[(size_t)(p3 & 0x1FFFF) * 32 + lane];
                if (affine) {
                    u0.x = fmaxf(fmaf(u0.x, s4.x, h4.x), 0.f); u0.y = fmaxf(fmaf(u0.y, s4.y, h4.y), 0.f);
                    u0.z = fmaxf(fmaf(u0.z, s4.z, h4.z), 0.f); u0.w = fmaxf(fmaf(u0.w, s4.w, h4.w), 0.f);
                    u1.x = fmaxf(fmaf(u1.x, s4.x, h4.x), 0.f); u1.y = fmaxf(fmaf(u1.y, s4.y, h4.y), 0.f);
                    u1.z = fmaxf(fmaf(u1.z, s4.z, h4.z), 0.f); u1.w = fmaxf(fmaf(u1.w, s4.w, h4.w), 0.f);
                    u2.x = fmaxf(fmaf(u2.x, s4.x, h4.x), 0.f); u2.y = fmaxf(fmaf(u2.y, s4.y, h4.y), 0.f);
                    u2.z = fmaxf(fmaf(u2.z, s4.z, h4.z), 0.f); u2.w = fmaxf(fmaf(u2.w, s4.w, h4.w), 0.f);
                    u3.x = fmaxf(fmaf(u3.x, s4.x, h4.x), 0.f); u3.y = fmaxf(fmaf(u3.y, s4.y, h4.y), 0.f);
                    u3.z = fmaxf(fmaf(u3.z, s4.z, h4.z), 0.f); u3.w = fmaxf(fmaf(u3.w, s4.w, h4.w), 0.f);
                }
                float4 c0 = comb[(p0 >> 17) * 32 + lane];
                float4 c1 = comb[(p1 >> 17) * 32 + lane];
                float4 c2 = comb[(p2 >> 17) * 32 + lane];
                float4 c3 = comb[(p3 >> 17) * 32 + lane];
                acc.x += (u0.x + c0.x) + (u1.x + c1.x) + (u2.x + c2.x) + (u3.x + c3.x);
                acc.y += (u0.y + c0.y) + (u1.y + c1.y) + (u2.y + c2.y) + (u3.y + c3.y);
                acc.z += (u0.z + c0.z) + (u1.z + c1.z) + (u2.z + c2.z) + (u3.z + c3.z);
                acc.w += (u0.w + c0.w) + (u1.w + c1.w) + (u2.w + c2.w) + (u3.w + c3.w);
            }
            for (; e < end; e++) {
                int p = g_eperm[e];
                float4 u = src4[(size_t)(p & 0x1FFFF) * 32 + lane];
                if (affine) {
                    u.x = fmaxf(fmaf(u.x, s4.x, h4.x), 0.f); u.y = fmaxf(fmaf(u.y, s4.y, h4.y), 0.f);
                    u.z = fmaxf(fmaf(u.z, s4.z, h4.z), 0.f); u.w = fmaxf(fmaf(u.w, s4.w, h4.w), 0.f);
                }
                float4 c = comb[(p >> 17) * 32 + lane];
                acc.x += u.x + c.x; acc.y += u.y + c.y;
                acc.z += u.z + c.z; acc.w += u.w + c.w;
            }
            uint32_t hi0, lo0, hi1, lo1;
            split2(acc.x, acc.y, hi0, lo0);
            split2(acc.z, acc.w, hi1, lo1);
            int rl = w * 8 + j;
            *(uint2*)&A1H[rl * 68 + 2 * lane] = make_uint2(hi0, hi1);
            *(uint2*)&A1L[rl * 68 + 2 * lane] = make_uint2(lo0, lo1);
        }
    }
    CPWAIT0();
    __syncthreads();

    // ---- GEMM1: C1[128,256] = A1[128,128] @ W1^T ----
    const uint32_t a1hS = sm2u(A1H), a1lS = sm2u(A1L);
    const uint32_t a2hS = sm2u(A2H), a2lS = sm2u(A2L);
    const uint32_t b2hS = sm2u(B2H), b2lS = sm2u(B2L);
    const int lx = lane & 15, hx = lane >> 4;
    const int r7 = lane & 7, p8 = (lane >> 3) & 1, n8 = lane >> 4;
    const uint32_t offA1 = ((wm * 32 + lx) * 68 + hx * 4) * 4;
    const uint32_t offB1 = ((wn * 64 + n8 * 8 + r7) * 68 + p8 * 4) * 4;
    const uint32_t offA2 = ((wm * 32 + lx) * 132 + hx * 4) * 4;
    const uint32_t offB2 = ((wn * 32 + n8 * 8 + r7) * 20 + p8 * 4) * 4;

    float c1[2][8][4];
    #pragma unroll
    for (int mt = 0; mt < 2; mt++)
        #pragma unroll
        for (int nt = 0; nt < 8; nt++)
            #pragma unroll
            for (int q = 0; q < 4; q++) c1[mt][nt][q] = 0.f;

    #pragma unroll
    for (int s = 0; s < 8; s++) {
        const uint32_t kb = s * 32;
        uint32_t ah[2][4], al[2][4];
        LDSM4(ah[0][0], ah[0][1], ah[0][2], ah[0][3], a1hS + offA1 + kb);
        LDSM4(ah[1][0], ah[1][1], ah[1][2], ah[1][3], a1hS + offA1 + 4352 + kb);
        LDSM4(al[0][0], al[0][1], al[0][2], al[0][3], a1lS + offA1 + kb);
        LDSM4(al[1][0], al[1][1], al[1][2], al[1][3], a1lS + offA1 + 4352 + kb);
        #pragma unroll
        for (int np = 0; np < 4; np++) {
            uint32_t bh[4], bl[4];
            LDSM4(bh[0], bh[1], bh[2], bh[3], b1hS + offB1 + np * 4352 + kb);
            LDSM4(bl[0], bl[1], bl[2], bl[3], b1lS + offB1 + np * 4352 + kb);
            #pragma unroll
            for (int mt = 0; mt < 2; mt++) {
                mma_bf16(c1[mt][2 * np],     ah[mt], bh);
                mma_bf16(c1[mt][2 * np],     ah[mt], bl);
                mma_bf16(c1[mt][2 * np],     al[mt], bh);
                mma_bf16(c1[mt][2 * np + 1], ah[mt], bh + 2);
                mma_bf16(c1[mt][2 * np + 1], ah[mt], bl + 2);
                mma_bf16(c1[mt][2 * np + 1], al[mt], bh + 2);
            }
        }
    }
    __syncthreads();

    // prefetch B2 chunk 0 while epilogue runs
    uint32_t qbh[4], qbl[4];
    #pragma unroll
    for (int it = 0; it < 4; it++) {
        int i = it * 512 + tid, r = i >> 4, p = i & 15;
        qbh[it] = w2h[r * 128 + p]; qbl[it] = w2l[r * 128 + p];
    }

    // epilogue1: +b1, relu, split -> A2
    #pragma unroll
    for (int mt = 0; mt < 2; mt++) {
        int r0 = wm * 32 + mt * 16 + g;
        #pragma unroll
        for (int nt = 0; nt < 8; nt++) {
            int cp = wn * 32 + nt * 4 + tig;
            float v0 = fmaxf(c1[mt][nt][0] + sb[2 * cp], 0.f);
            float v1 = fmaxf(c1[mt][nt][1] + sb[2 * cp + 1], 0.f);
            float v2 = fmaxf(c1[mt][nt][2] + sb[2 * cp], 0.f);
            float v3 = fmaxf(c1[mt][nt][3] + sb[2 * cp + 1], 0.f);
            uint32_t hi, lo;
            split2(v0, v1, hi, lo);
            A2H[r0 * A2_S + cp] = hi; A2L[r0 * A2_S + cp] = lo;
            split2(v2, v3, hi, lo);
            A2H[(r0 + 8) * A2_S + cp] = hi; A2L[(r0 + 8) * A2_S + cp] = lo;
        }
    }
    __syncthreads();

    // ---- GEMM2: C2[128,128] = A2[128,256] @ W2^T ----
    float c2[2][4][4];
    #pragma unroll
    for (int mt = 0; mt < 2; mt++)
        #pragma unroll
        for (int nt = 0; nt < 4; nt++)
            #pragma unroll
            for (int q = 0; q < 4; q++) c2[mt][nt][q] = 0.f;

    for (int kc = 0; kc < 8; kc++) {
        #pragma unroll
        for (int it = 0; it < 4; it++) {
            int i = it * 512 + tid, r = i >> 4, p = i & 15;
            B2H[r * 20 + p] = qbh[it]; B2L[r * 20 + p] = qbl[it];
        }
        __syncthreads();
        if (kc < 7) {
            #pragma unroll
            for (int it = 0; it < 4; it++) {
                int i = it * 512 + tid, r = i >> 4, p = i & 15;
                qbh[it] = w2h[r * 128 + (kc + 1) * 16 + p];
                qbl[it] = w2l[r * 128 + (kc + 1) * 16 + p];
            }
        }
        #pragma unroll
        for (int ks = 0; ks < 2; ks++) {
            const uint32_t kbA = (kc * 16 + ks * 8) * 4;
            const uint32_t kb4 = ks * 32;
            uint32_t ah[2][4], al[2][4];
            LDSM4(ah[0][0], ah[0][1], ah[0][2], ah[0][3], a2hS + offA2 + kbA);
            LDSM4(ah[1][0], ah[1][1], ah[1][2], ah[1][3], a2hS + offA2 + 8448 + kbA);
            LDSM4(al[0][0], al[0][1], al[0][2], al[0][3], a2lS + offA2 + kbA);
            LDSM4(al[1][0], al[1][1], al[1][2], al[1][3], a2lS + offA2 + 8448 + kbA);
            #pragma unroll
            for (int np = 0; np < 2; np++) {
                uint32_t bh[4], bl[4];
                LDSM4(bh[0], bh[1], bh[2], bh[3], b2hS + offB2 + np * 1280 + kb4);
                LDSM4(bl[0], bl[1], bl[2], bl[3], b2lS + offB2 + np * 1280 + kb4);
                #pragma unroll
                for (int mt = 0; mt < 2; mt++) {
                    mma_bf16(c2[mt][2 * np],     ah[mt], bh);
                    mma_bf16(c2[mt][2 * np],     ah[mt], bl);
                    mma_bf16(c2[mt][2 * np],     al[mt], bh);
                    mma_bf16(c2[mt][2 * np + 1], ah[mt], bh + 2);
                    mma_bf16(c2[mt][2 * np + 1], ah[mt], bl + 2);
                    mma_bf16(c2[mt][2 * np + 1], al[mt], bh + 2);
                }
            }
        }
        __syncthreads();
    }

    // epilogue2: +b2 -> hout, BN partial sums
    float* hm = hout + rowbase * DD;
    float sA[4][2], qA[4][2];
    #pragma unroll
    for (int nt = 0; nt < 4; nt++) { sA[nt][0] = sA[nt][1] = qA[nt][0] = qA[nt][1] = 0.f; }
    #pragma unroll
    for (int mt = 0; mt < 2; mt++) {
        int r0 = wm * 32 + mt * 16 + g;
        #pragma unroll
        for (int nt = 0; nt < 4; nt++) {
            int col = wn * 32 + nt * 8 + 2 * tig;
            float v00 = c2[mt][nt][0] + sb[256 + col];
            float v01 = c2[mt][nt][1] + sb[256 + col + 1];
            float v10 = c2[mt][nt][2] + sb[256 + col];
            float v11 = c2[mt][nt][3] + sb[256 + col + 1];
            *(float2*)&hm[r0 * DD + col] = make_float2(v00, v01);
            *(float2*)&hm[(r0 + 8) * DD + col] = make_float2(v10, v11);
            sA[nt][0] += v00 + v10; qA[nt][0] += v00 * v00 + v10 * v10;
            sA[nt][1] += v01 + v11; qA[nt][1] += v01 * v01 + v11 * v11;
        }
    }
    #pragma unroll
    for (int nt = 0; nt < 4; nt++)
        #pragma unroll
        for (int p = 0; p < 2; p++) {
            float s = sA[nt][p], q = qA[nt][p];
            #pragma unroll
            for (int o = 16; o >= 4; o >>= 1) {
                s += __shfl_xor_sync(0xFFFFFFFFu, s, o);
                q += __shfl_xor_sync(0xFFFFFFFFu, q, o);
            }
            if (g == 0) {
                int col = wn * 32 + nt * 8 + 2 * tig + p;
                atomicAdd(&bnd[col], (double)s);
                atomicAdd(&bnd[128 + col], (double)q);
            }
        }
    __syncthreads();
    if (tid < 256) atomicAdd(&g_sumsd[tid], bnd[tid]);
}

// ------------------------- launch -------------------------------------------
extern "C" void kernel_launch(void* const* d_in, const int* in_sizes, int n_in,
                              void* d_out, int out_size) {
    const int*   x    = (const int*)d_in[0];
    const int*   ei   = (const int*)d_in[1];
    const int*   ea   = (const int*)d_in[2];
    const float* xe1  = (const float*)d_in[3];
    const float* xe2  = (const float*)d_in[4];
    const float* ee1  = (const float*)d_in[5];
    const float* ee2  = (const float*)d_in[6];
    const float* W1   = (const float*)d_in[7];
    const float* b1   = (const float*)d_in[8];
    const float* W2   = (const float*)d_in[9];
    const float* b2   = (const float*)d_in[10];
    const float* gam  = (const float*)d_in[11];
    const float* bet  = (const float*)d_in[12];
    float* out = (float*)d_out;

    cudaFuncSetAttribute(k_fused, cudaFuncAttributeMaxDynamicSharedMemorySize, SM_TOT);

    k_prep<<<640, 256>>>(W1, W2);
    k_inithist<<<16384, 256>>>(x, xe1, xe2, ei);
    k_scanplace<<<1, 1024>>>(ei, ea);

    static const int srcsel[LL] = {0, 1, 2, 1, 2};
    static const int dstsel[LL] = {1, 2, 1, 2, 1};
    for (int l = 0; l < LL; l++) {
        k_fused<<<1024, 512, SM_TOT>>>(srcsel[l], dstsel[l],
                                       ee1 + (size_t)l * 6 * DD, ee2 + (size_t)l * 3 * DD,
                                       b1 + l * 256, b2 + l * 128,
                                       l > 0 ? 1 : 0, l);
        k_stats<<<1, 128>>>(gam + l * DD, bet + l * DD);
    }
    k_final<<<16384, 256>>>(out);
}

// round 16
// speedup vs baseline: 1.4744x; 1.4744x over previous
#include <cuda_runtime.h>
#include <cuda_bf16.h>
#include <cstdint>

#define NN 131072
#define NE 262144
#define DD 128
#define LL 5

// ------------------------- scratch (device globals) ------------------------
__device__ float g_h0[(size_t)NN * DD];
__device__ float g_bufA[(size_t)NN * DD];
__device__ float g_bufB[(size_t)NN * DD];
__device__ uint32_t g_a1h[(size_t)NN * 64];  // agg out, bf16x2 hi pairs
__device__ uint32_t g_a1l[(size_t)NN * 64];  // lo
__device__ uint32_t g_w1h[LL * 256 * 64];    // [l][n][k2] bf16x2 hi
__device__ uint32_t g_w1l[LL * 256 * 64];
__device__ uint32_t g_w2h[LL * 128 * 128];
__device__ uint32_t g_w2l[LL * 128 * 128];
__device__ double g_sumsd[256];
__device__ float g_ss[256];
// CSR scratch
__device__ int g_deg[NN];                    // degree -> cursor
__device__ int g_rowptr[NN + 1];
__device__ int g_bsum[128];
__device__ int g_eperm[NE];                  // src | (combo<<17)

// ------------------------- helpers -----------------------------------------
__device__ __forceinline__ uint32_t sm2u(const void* p) {
    uint32_t a;
    asm("{ .reg .u64 t; cvta.to.shared.u64 t, %1; cvt.u32.u64 %0, t; }" : "=r"(a) : "l"(p));
    return a;
}
#define LDSM4(d0, d1, d2, d3, a) \
    asm volatile("ldmatrix.sync.aligned.m8n8.x4.shared.b16 {%0,%1,%2,%3}, [%4];" \
                 : "=r"(d0), "=r"(d1), "=r"(d2), "=r"(d3) : "r"(a))
#define CPASYNC16(dst, src) \
    asm volatile("cp.async.cg.shared.global [%0], [%1], 16;" :: "r"(dst), "l"(src) : "memory")
#define CPCOMMIT() asm volatile("cp.async.commit_group;" ::: "memory")
#define CPWAIT0()  asm volatile("cp.async.wait_group 0;" ::: "memory")

__device__ __forceinline__ void split2(float v0, float v1, uint32_t& hi, uint32_t& lo) {
    __nv_bfloat16 h0 = __float2bfloat16_rn(v0), h1 = __float2bfloat16_rn(v1);
    __nv_bfloat162 hp; hp.x = h0; hp.y = h1;
    hi = *(uint32_t*)&hp;
    float l0 = v0 - __bfloat162float(h0), l1 = v1 - __bfloat162float(h1);
    __nv_bfloat162 lp = __floats2bfloat162_rn(l0, l1);
    lo = *(uint32_t*)&lp;
}
__device__ __forceinline__ void mma_bf16(float* d, const uint32_t* a, const uint32_t* b) {
    asm volatile(
        "mma.sync.aligned.m16n8k16.row.col.f32.bf16.bf16.f32 "
        "{%0,%1,%2,%3}, {%4,%5,%6,%7}, {%8,%9}, {%0,%1,%2,%3};"
        : "+f"(d[0]), "+f"(d[1]), "+f"(d[2]), "+f"(d[3])
        : "r"(a[0]), "r"(a[1]), "r"(a[2]), "r"(a[3]), "r"(b[0]), "r"(b[1]));
}

// ------------------------- prep: weights + zeroing --------------------------
__global__ void k_prep(const float* __restrict__ W1, const float* __restrict__ W2) {
    int i = blockIdx.x * 256 + threadIdx.x;              // 640*256 = 163840
    if (i < 81920) {
        int l = i / 16384, r = i - l * 16384;
        int n = r >> 6, k2 = r & 63;
        float w0 = W1[l * 32768 + (2 * k2) * 256 + n];
        float w1 = W1[l * 32768 + (2 * k2 + 1) * 256 + n];
        uint32_t hi, lo; split2(w0, w1, hi, lo);
        g_w1h[i] = hi; g_w1l[i] = lo;
    } else {
        int j = i - 81920;
        int l = j / 16384, r = j - l * 16384;
        int n = r >> 7, k2 = r & 127;
        float w0 = W2[l * 32768 + (2 * k2) * 128 + n];
        float w1 = W2[l * 32768 + (2 * k2 + 1) * 128 + n];
        uint32_t hi, lo; split2(w0, w1, hi, lo);
        g_w2h[j] = hi; g_w2l[j] = lo;
    }
    if (i < NN) g_deg[i] = 0;
    if (i < 128) { g_sumsd[2 * i] = 0.0; g_sumsd[2 * i + 1] = 0.0; }
}

// ------------------------- init h0 + edge histogram -------------------------
__global__ void k_inithist(const int* __restrict__ x, const float* __restrict__ xe1,
                           const float* __restrict__ xe2, const int* __restrict__ ei) {
    int t = blockIdx.x * 256 + threadIdx.x;              // NN*32
    int row = t >> 5, c4 = t & 31;
    int i0 = x[2 * row], i1 = x[2 * row + 1];
    float4 a = ((const float4*)xe1)[i0 * 32 + c4];
    float4 b = ((const float4*)xe2)[i1 * 32 + c4];
    ((float4*)g_h0)[t] = make_float4(a.x + b.x, a.y + b.y, a.z + b.z, a.w + b.w);
    if (t < NE) atomicAdd(&g_deg[ei[NE + t]], 1);
}

// ------------------------- CSR scan (parallel) ------------------------------
__global__ void __launch_bounds__(1024) k_scan1() {      // 128 blocks x 1024
    __shared__ int s[1024];
    int t = threadIdx.x, i = blockIdx.x * 1024 + t;
    s[t] = g_deg[i];
    __syncthreads();
    #pragma unroll
    for (int off = 1; off < 1024; off <<= 1) {
        int x = (t >= off) ? s[t - off] : 0;
        __syncthreads();
        s[t] += x;
        __syncthreads();
    }
    g_rowptr[i + 1] = s[t];                              // block-local inclusive
    if (t == 1023) g_bsum[blockIdx.x] = s[1023];
}
__global__ void k_scan23() {                             // 512 blocks x 256
    __shared__ int sbase;
    int t = threadIdx.x, i = blockIdx.x * 256 + t;
    int chunk = blockIdx.x >> 2;                         // constant per block
    if (t == 0) {
        int b = 0;
        for (int k = 0; k < chunk; k++) b += g_bsum[k];
        sbase = b;
    }
    __syncthreads();
    int incl = g_rowptr[i + 1] + sbase;
    g_rowptr[i + 1] = incl;
    g_deg[i] = incl - g_deg[i];                          // cursor = exclusive start
    if (i == 0) g_rowptr[0] = 0;
}
__global__ void k_place(const int* __restrict__ ei, const int* __restrict__ ea) {
    int e = blockIdx.x * 256 + threadIdx.x;
    int dst = ei[NE + e];
    int src = ei[e];
    int combo = ea[2 * e] * 3 + ea[2 * e + 1];
    int pos = atomicAdd(&g_deg[dst], 1);
    g_eperm[pos] = src | (combo << 17);
}

// ------------------------- aggregation (high-occupancy, split output) -------
__global__ void __launch_bounds__(256) k_agg(
    int src_sel, const float* __restrict__ e1, const float* __restrict__ e2, int affine)
{
    __shared__ float4 comb[18 * 32];
    __shared__ float4 ssc[32], ssh[32];
    int tid = threadIdx.x;
    for (int i = tid; i < 18 * 32; i += 256) {
        int cb = i >> 5, c4 = i & 31;
        int a0 = cb / 3, a1 = cb - a0 * 3;
        float4 v1 = ((const float4*)e1)[a0 * 32 + c4];
        float4 v2 = ((const float4*)e2)[a1 * 32 + c4];
        comb[i] = make_float4(v1.x + v2.x, v1.y + v2.y, v1.z + v2.z, v1.w + v2.w);
    }
    if (tid < 32) {
        if (affine) {
            ssc[tid] = ((const float4*)g_ss)[tid];
            ssh[tid] = ((const float4*)g_ss)[32 + tid];
        } else {
            ssc[tid] = make_float4(1.f, 1.f, 1.f, 1.f);
            ssh[tid] = make_float4(0.f, 0.f, 0.f, 0.f);
        }
    }
    __syncthreads();
    int lane = tid & 31;
    int node = blockIdx.x * 8 + (tid >> 5);
    const float* hsrc = (src_sel == 0) ? g_h0 : (src_sel == 1 ? g_bufA : g_bufB);
    const float4* src4 = (const float4*)hsrc;
    float4 s4 = ssc[lane], h4 = ssh[lane];
    float4 v = src4[(size_t)node * 32 + lane];
    float4 acc;
    if (affine) {
        acc.x = fmaxf(fmaf(v.x, s4.x, h4.x), 0.f);
        acc.y = fmaxf(fmaf(v.y, s4.y, h4.y), 0.f);
        acc.z = fmaxf(fmaf(v.z, s4.z, h4.z), 0.f);
        acc.w = fmaxf(fmaf(v.w, s4.w, h4.w), 0.f);
    } else acc = v;
    float4 cm = comb[12 * 32 + lane];
    acc.x += cm.x; acc.y += cm.y; acc.z += cm.z; acc.w += cm.w;

    int beg = g_rowptr[node], end = g_rowptr[node + 1];
    int e = beg;
    for (; e + 3 < end; e += 4) {
        int p0 = g_eperm[e],     p1 = g_eperm[e + 1];
        int p2 = g_eperm[e + 2], p3 = g_eperm[e + 3];
        float4 u0 = src4[(size_t)(p0 & 0x1FFFF) * 32 + lane];
        float4 u1 = src4[(size_t)(p1 & 0x1FFFF) * 32 + lane];
        float4 u2 = src4[(size_t)(p2 & 0x1FFFF) * 32 + lane];
        float4 u3 = src4[(size_t)(p3 & 0x1FFFF) * 32 + lane];
        if (affine) {
            u0.x = fmaxf(fmaf(u0.x, s4.x, h4.x), 0.f); u0.y = fmaxf(fmaf(u0.y, s4.y, h4.y), 0.f);
            u0.z = fmaxf(fmaf(u0.z, s4.z, h4.z), 0.f); u0.w = fmaxf(fmaf(u0.w, s4.w, h4.w), 0.f);
            u1.x = fmaxf(fmaf(u1.x, s4.x, h4.x), 0.f); u1.y = fmaxf(fmaf(u1.y, s4.y, h4.y), 0.f);
            u1.z = fmaxf(fmaf(u1.z, s4.z, h4.z), 0.f); u1.w = fmaxf(fmaf(u1.w, s4.w, h4.w), 0.f);
            u2.x = fmaxf(fmaf(u2.x, s4.x, h4.x), 0.f); u2.y = fmaxf(fmaf(u2.y, s4.y, h4.y), 0.f);
            u2.z = fmaxf(fmaf(u2.z, s4.z, h4.z), 0.f); u2.w = fmaxf(fmaf(u2.w, s4.w, h4.w), 0.f);
            u3.x = fmaxf(fmaf(u3.x, s4.x, h4.x), 0.f); u3.y = fmaxf(fmaf(u3.y, s4.y, h4.y), 0.f);
            u3.z = fmaxf(fmaf(u3.z, s4.z, h4.z), 0.f); u3.w = fmaxf(fmaf(u3.w, s4.w, h4.w), 0.f);
        }
        float4 c0 = comb[(p0 >> 17) * 32 + lane];
        float4 c1 = comb[(p1 >> 17) * 32 + lane];
        float4 c2 = comb[(p2 >> 17) * 32 + lane];
        float4 c3 = comb[(p3 >> 17) * 32 + lane];
        acc.x += (u0.x + c0.x) + (u1.x + c1.x) + (u2.x + c2.x) + (u3.x + c3.x);
        acc.y += (u0.y + c0.y) + (u1.y + c1.y) + (u2.y + c2.y) + (u3.y + c3.y);
        acc.z += (u0.z + c0.z) + (u1.z + c1.z) + (u2.z + c2.z) + (u3.z + c3.z);
        acc.w += (u0.w + c0.w) + (u1.w + c1.w) + (u2.w + c2.w) + (u3.w + c3.w);
    }
    for (; e < end; e++) {
        int p = g_eperm[e];
        float4 u = src4[(size_t)(p & 0x1FFFF) * 32 + lane];
        if (affine) {
            u.x = fmaxf(fmaf(u.x, s4.x, h4.x), 0.f); u.y = fmaxf(fmaf(u.y, s4.y, h4.y), 0.f);
            u.z = fmaxf(fmaf(u.z, s4.z, h4.z), 0.f); u.w = fmaxf(fmaf(u.w, s4.w, h4.w), 0.f);
        }
        float4 c = comb[(p >> 17) * 32 + lane];
        acc.x += u.x + c.x; acc.y += u.y + c.y;
        acc.z += u.z + c.z; acc.w += u.w + c.w;
    }
    uint32_t hi0, lo0, hi1, lo1;
    split2(acc.x, acc.y, hi0, lo0);
    split2(acc.z, acc.w, hi1, lo1);
    *(uint2*)&g_a1h[(size_t)node * 64 + 2 * lane] = make_uint2(hi0, hi1);
    *(uint2*)&g_a1l[(size_t)node * 64 + 2 * lane] = make_uint2(lo0, lo1);
}

// ------------------------- BN stats / final ---------------------------------
__global__ void k_stats(const float* __restrict__ gamma, const float* __restrict__ beta) {
    int c = threadIdx.x;
    double su = g_sumsd[c], sq = g_sumsd[128 + c];
    double mu  = su * (1.0 / NN);
    double var = sq * (1.0 / NN) - mu * mu;
    float sc = (float)(rsqrt(var + 1e-5) * (double)gamma[c]);
    g_ss[c] = sc;
    g_ss[128 + c] = (float)((double)beta[c] - mu * (double)sc);
    g_sumsd[c] = 0.0; g_sumsd[128 + c] = 0.0;
}
__global__ void k_final(float* __restrict__ out) {
    int t = blockIdx.x * 256 + threadIdx.x;
    int c4 = t & 31;
    float4 v = ((const float4*)g_bufA)[t];
    float4 s = ((const float4*)g_ss)[c4];
    float4 b = ((const float4*)g_ss)[32 + c4];
    ((float4*)out)[t] = make_float4(fmaf(v.x, s.x, b.x), fmaf(v.y, s.y, b.y),
                                    fmaf(v.z, s.z, b.z), fmaf(v.w, s.w, b.w));
}

// ------------------------- GEMM kernel (cp.async A1+W1) ---------------------
#define A1H_OFF 0           // 128 x 68 u32   [phase 1]
#define A1L_OFF 34816
#define B1H_OFF 69632       // 256 x 68 u32   [phase 1]
#define B1L_OFF 139264
#define A2H_OFF 0           // 128 x 132 u32  [phase 2]
#define A2L_OFF 67584
#define A2_S    132
#define B2H_OFF 135168      // 128 x 20 u32   [phase 2]
#define B2L_OFF 145408
#define SB_OFF  208896      // 384 floats
#define BND_OFF 210432      // 256 doubles
#define SM_TOT  212480

__global__ void __launch_bounds__(512, 1) k_gemm(
    int dst_sel, const float* __restrict__ b1p, const float* __restrict__ b2p, int layer)
{
    extern __shared__ char smem[];
    uint32_t* A2H = (uint32_t*)(smem + A2H_OFF);
    uint32_t* A2L = (uint32_t*)(smem + A2L_OFF);
    uint32_t* B2H = (uint32_t*)(smem + B2H_OFF);
    uint32_t* B2L = (uint32_t*)(smem + B2L_OFF);
    float*    sb  = (float*)(smem + SB_OFF);
    double*   bnd = (double*)(smem + BND_OFF);
    const int tid = threadIdx.x, w = tid >> 5, lane = tid & 31;
    const int g = lane >> 2, tig = lane & 3;
    const int wm = w & 3, wn = w >> 2;
    const uint32_t* w1h = g_w1h + layer * 16384;
    const uint32_t* w1l = g_w1l + layer * 16384;
    const uint32_t* w2h = g_w2h + layer * 16384;
    const uint32_t* w2l = g_w2l + layer * 16384;
    const size_t rowbase = (size_t)blockIdx.x * 128;
    float* hout = (dst_sel == 1) ? g_bufA : g_bufB;

    // ---- cp.async: A1 (this tile, 128 rows x 16 segs) + W1 (full) ----
    const uint32_t a1hS = sm2u(smem + A1H_OFF), a1lS = sm2u(smem + A1L_OFF);
    const uint32_t b1hS = sm2u(smem + B1H_OFF), b1lS = sm2u(smem + B1L_OFF);
    #pragma unroll
    for (int it = 0; it < 4; it++) {                     // 4*512 = 2048 = 128 rows x 16 segs
        int i = it * 512 + tid, r = i >> 4, seg = (i & 15) * 4;
        CPASYNC16(a1hS + (r * 68 + seg) * 4, g_a1h + (rowbase + r) * 64 + seg);
        CPASYNC16(a1lS + (r * 68 + seg) * 4, g_a1l + (rowbase + r) * 64 + seg);
    }
    #pragma unroll
    for (int it = 0; it < 8; it++) {                     // 256 rows x 16 segs
        int i = it * 512 + tid, r = i >> 4, seg = (i & 15) * 4;
        CPASYNC16(b1hS + (r * 68 + seg) * 4, w1h + r * 64 + seg);
        CPASYNC16(b1lS + (r * 68 + seg) * 4, w1l + r * 64 + seg);
    }
    CPCOMMIT();

    if (tid < 384) sb[tid] = (tid < 256) ? b1p[tid] : b2p[tid - 256];
    if (tid < 256) bnd[tid] = 0.0;

    // ldmatrix per-lane offsets
    const uint32_t a2hS = sm2u(A2H), a2lS = sm2u(A2L);
    const uint32_t b2hS = sm2u(B2H), b2lS = sm2u(B2L);
    const int lx = lane & 15, hx = lane >> 4;
    const int r7 = lane & 7, p8 = (lane >> 3) & 1, n8 = lane >> 4;
    const uint32_t offA1 = ((wm * 32 + lx) * 68 + hx * 4) * 4;
    const uint32_t offB1 = ((wn * 64 + n8 * 8 + r7) * 68 + p8 * 4) * 4;
    const uint32_t offA2 = ((wm * 32 + lx) * 132 + hx * 4) * 4;
    const uint32_t offB2 = ((wn * 32 + n8 * 8 + r7) * 20 + p8 * 4) * 4;

    float c1[2][8][4];
    #pragma unroll
    for (int mt = 0; mt < 2; mt++)
        #pragma unroll
        for (int nt = 0; nt < 8; nt++)
            #pragma unroll
            for (int q = 0; q < 4; q++) c1[mt][nt][q] = 0.f;

    CPWAIT0();
    __syncthreads();

    // ---- GEMM1: C1[128,256] = A1[128,128] @ W1^T ----
    #pragma unroll
    for (int s = 0; s < 8; s++) {
        const uint32_t kb = s * 32;
        uint32_t ah[2][4], al[2][4];
        LDSM4(ah[0][0], ah[0][1], ah[0][2], ah[0][3], a1hS + offA1 + kb);
        LDSM4(ah[1][0], ah[1][1], ah[1][2], ah[1][3], a1hS + offA1 + 4352 + kb);
        LDSM4(al[0][0], al[0][1], al[0][2], al[0][3], a1lS + offA1 + kb);
        LDSM4(al[1][0], al[1][1], al[1][2], al[1][3], a1lS + offA1 + 4352 + kb);
        #pragma unroll
        for (int np = 0; np < 4; np++) {
            uint32_t bh[4], bl[4];
            LDSM4(bh[0], bh[1], bh[2], bh[3], b1hS + offB1 + np * 4352 + kb);
            LDSM4(bl[0], bl[1], bl[2], bl[3], b1lS + offB1 + np * 4352 + kb);
            #pragma unroll
            for (int mt = 0; mt < 2; mt++) {
                mma_bf16(c1[mt][2 * np],     ah[mt], bh);
                mma_bf16(c1[mt][2 * np],     ah[mt], bl);
                mma_bf16(c1[mt][2 * np],     al[mt], bh);
                mma_bf16(c1[mt][2 * np + 1], ah[mt], bh + 2);
                mma_bf16(c1[mt][2 * np + 1], ah[mt], bl + 2);
                mma_bf16(c1[mt][2 * np + 1], al[mt], bh + 2);
            }
        }
    }
    __syncthreads();

    // prefetch B2 chunk 0
    uint32_t qbh[4], qbl[4];
    #pragma unroll
    for (int it = 0; it < 4; it++) {
        int i = it * 512 + tid, r = i >> 4, p = i & 15;
        qbh[it] = w2h[r * 128 + p]; qbl[it] = w2l[r * 128 + p];
    }

    // epilogue1: +b1, relu, split -> A2
    #pragma unroll
    for (int mt = 0; mt < 2; mt++) {
        int r0 = wm * 32 + mt * 16 + g;
        #pragma unroll
        for (int nt = 0; nt < 8; nt++) {
            int cp = wn * 32 + nt * 4 + tig;
            float v0 = fmaxf(c1[mt][nt][0] + sb[2 * cp], 0.f);
            float v1 = fmaxf(c1[mt][nt][1] + sb[2 * cp + 1], 0.f);
            float v2 = fmaxf(c1[mt][nt][2] + sb[2 * cp], 0.f);
            float v3 = fmaxf(c1[mt][nt][3] + sb[2 * cp + 1], 0.f);
            uint32_t hi, lo;
            split2(v0, v1, hi, lo);
            A2H[r0 * A2_S + cp] = hi; A2L[r0 * A2_S + cp] = lo;
            split2(v2, v3, hi, lo);
            A2H[(r0 + 8) * A2_S + cp] = hi; A2L[(r0 + 8) * A2_S + cp] = lo;
        }
    }
    __syncthreads();

    // ---- GEMM2: C2[128,128] = A2[128,256] @ W2^T ----
    float c2[2][4][4];
    #pragma unroll
    for (int mt = 0; mt < 2; mt++)
        #pragma unroll
        for (int nt = 0; nt < 4; nt++)
            #pragma unroll
            for (int q = 0; q < 4; q++) c2[mt][nt][q] = 0.f;

    for (int kc = 0; kc < 8; kc++) {
        #pragma unroll
        for (int it = 0; it < 4; it++) {
            int i = it * 512 + tid, r = i >> 4, p = i & 15;
            B2H[r * 20 + p] = qbh[it]; B2L[r * 20 + p] = qbl[it];
        }
        __syncthreads();
        if (kc < 7) {
            #pragma unroll
            for (int it = 0; it < 4; it++) {
                int i = it * 512 + tid, r = i >> 4, p = i & 15;
                qbh[it] = w2h[r * 128 + (kc + 1) * 16 + p];
                qbl[it] = w2l[r * 128 + (kc + 1) * 16 + p];
            }
        }
        #pragma unroll
        for (int ks = 0; ks < 2; ks++) {
            const uint32_t kbA = (kc * 16 + ks * 8) * 4;
            const uint32_t kb4 = ks * 32;
            uint32_t ah[2][4], al[2][4];
            LDSM4(ah[0][0], ah[0][1], ah[0][2], ah[0][3], a2hS + offA2 + kbA);
            LDSM4(ah[1][0], ah[1][1], ah[1][2], ah[1][3], a2hS + offA2 + 8448 + kbA);
            LDSM4(al[0][0], al[0][1], al[0][2], al[0][3], a2lS + offA2 + kbA);
            LDSM4(al[1][0], al[1][1], al[1][2], al[1][3], a2lS + offA2 + 8448 + kbA);
            #pragma unroll
            for (int np = 0; np < 2; np++) {
                uint32_t bh[4], bl[4];
                LDSM4(bh[0], bh[1], bh[2], bh[3], b2hS + offB2 + np * 1280 + kb4);
                LDSM4(bl[0], bl[1], bl[2], bl[3], b2lS + offB2 + np * 1280 + kb4);
                #pragma unroll
                for (int mt = 0; mt < 2; mt++) {
                    mma_bf16(c2[mt][2 * np],     ah[mt], bh);
                    mma_bf16(c2[mt][2 * np],     ah[mt], bl);
                    mma_bf16(c2[mt][2 * np],     al[mt], bh);
                    mma_bf16(c2[mt][2 * np + 1], ah[mt], bh + 2);
                    mma_bf16(c2[mt][2 * np + 1], ah[mt], bl + 2);
                    mma_bf16(c2[mt][2 * np + 1], al[mt], bh + 2);
                }
            }
        }
        __syncthreads();
    }

    // epilogue2: +b2 -> hout, BN partial sums
    float* hm = hout + rowbase * DD;
    float sA[4][2], qA[4][2];
    #pragma unroll
    for (int nt = 0; nt < 4; nt++) { sA[nt][0] = sA[nt][1] = qA[nt][0] = qA[nt][1] = 0.f; }
    #pragma unroll
    for (int mt = 0; mt < 2; mt++) {
        int r0 = wm * 32 + mt * 16 + g;
        #pragma unroll
        for (int nt = 0; nt < 4; nt++) {
            int col = wn * 32 + nt * 8 + 2 * tig;
            float v00 = c2[mt][nt][0] + sb[256 + col];
            float v01 = c2[mt][nt][1] + sb[256 + col + 1];
            float v10 = c2[mt][nt][2] + sb[256 + col];
            float v11 = c2[mt][nt][3] + sb[256 + col + 1];
            *(float2*)&hm[r0 * DD + col] = make_float2(v00, v01);
            *(float2*)&hm[(r0 + 8) * DD + col] = make_float2(v10, v11);
            sA[nt][0] += v00 + v10; qA[nt][0] += v00 * v00 + v10 * v10;
            sA[nt][1] += v01 + v11; qA[nt][1] += v01 * v01 + v11 * v11;
        }
    }
    #pragma unroll
    for (int nt = 0; nt < 4; nt++)
        #pragma unroll
        for (int p = 0; p < 2; p++) {
            float s = sA[nt][p], q = qA[nt][p];
            #pragma unroll
            for (int o = 16; o >= 4; o >>= 1) {
                s += __shfl_xor_sync(0xFFFFFFFFu, s, o);
                q += __shfl_xor_sync(0xFFFFFFFFu, q, o);
            }
            if (g == 0) {
                int col = wn * 32 + nt * 8 + 2 * tig + p;
                atomicAdd(&bnd[col], (double)s);
                atomicAdd(&bnd[128 + col], (double)q);
            }
        }
    __syncthreads();
    if (tid < 256) atomicAdd(&g_sumsd[tid], bnd[tid]);
}

// ------------------------- launch -------------------------------------------
extern "C" void kernel_launch(void* const* d_in, const int* in_sizes, int n_in,
                              void* d_out, int out_size) {
    const int*   x    = (const int*)d_in[0];
    const int*   ei   = (const int*)d_in[1];
    const int*   ea   = (const int*)d_in[2];
    const float* xe1  = (const float*)d_in[3];
    const float* xe2  = (const float*)d_in[4];
    const float* ee1  = (const float*)d_in[5];
    const float* ee2  = (const float*)d_in[6];
    const float* W1   = (const float*)d_in[7];
    const float* b1   = (const float*)d_in[8];
    const float* W2   = (const float*)d_in[9];
    const float* b2   = (const float*)d_in[10];
    const float* gam  = (const float*)d_in[11];
    const float* bet  = (const float*)d_in[12];
    float* out = (float*)d_out;

    cudaFuncSetAttribute(k_gemm, cudaFuncAttributeMaxDynamicSharedMemorySize, SM_TOT);

    k_prep<<<640, 256>>>(W1, W2);
    k_inithist<<<16384, 256>>>(x, xe1, xe2, ei);
    k_scan1<<<128, 1024>>>();
    k_scan23<<<512, 256>>>();
    k_place<<<1024, 256>>>(ei, ea);

    static const int srcsel[LL] = {0, 1, 2, 1, 2};
    static const int dstsel[LL] = {1, 2, 1, 2, 1};
    for (int l = 0; l < LL; l++) {
        k_agg<<<16384, 256>>>(srcsel[l],
                              ee1 + (size_t)l * 6 * DD, ee2 + (size_t)l * 3 * DD,
                              l > 0 ? 1 : 0);
        k_gemm<<<1024, 512, SM_TOT>>>(dstsel[l], b1 + l * 256, b2 + l * 128, l);
        k_stats<<<1, 128>>>(gam + l * DD, bet + l * DD);
    }
    k_final<<<16384, 256>>>(out);
}